// round 14
// baseline (speedup 1.0000x reference)
#include <cuda_runtime.h>
#include <math.h>
#include <cstdint>

// Problem dims
#define Bq 8
#define Tq 1024
#define Cq 768
#define Hq 12
#define Dq 64

// Scratch (device globals: allocation-free rule)
__device__ float g_qkv[(size_t)Bq * Tq * 3 * Cq];   // [B*T][2304]
__device__ float g_q[(size_t)Bq * Hq * Tq * Dq];    // [B][H][T][D] (tf32-rounded)
__device__ float g_k[(size_t)Bq * Hq * Tq * Dq];
__device__ float g_v[(size_t)Bq * Hq * Tq * Dq];
__device__ float g_att[(size_t)Bq * Tq * Cq];       // [B][T][C]   (tf32-rounded)
__device__ float g_xr[(size_t)Bq * Tq * Cq];        // rounded x
__device__ float g_wqkv_r[(size_t)3 * Cq * Cq];     // rounded w_qkv
__device__ float g_wproj_r[(size_t)Cq * Cq];        // rounded w_proj

// ---------------------------------------------------------------------------
// Helpers
// ---------------------------------------------------------------------------
__device__ __forceinline__ uint32_t smem_u32(const void* p) {
    uint32_t a;
    asm("{ .reg .u64 t; cvta.to.shared.u64 t, %1; cvt.u32.u64 %0, t; }"
        : "=r"(a) : "l"(p));
    return a;
}

__device__ __forceinline__ uint32_t cvt_tf32(float v) {
    uint32_t u;
    asm("cvt.rna.tf32.f32 %0, %1;" : "=r"(u) : "f"(v));
    return u;
}

__device__ __forceinline__ void mma_tf32(float* d, const uint32_t* a,
                                         const uint32_t* b) {
    asm volatile(
        "mma.sync.aligned.m16n8k8.row.col.f32.tf32.tf32.f32 "
        "{%0,%1,%2,%3}, {%4,%5,%6,%7}, {%8,%9}, {%0,%1,%2,%3};"
        : "+f"(d[0]), "+f"(d[1]), "+f"(d[2]), "+f"(d[3])
        : "r"(a[0]), "r"(a[1]), "r"(a[2]), "r"(a[3]), "r"(b[0]), "r"(b[1]));
}

// ldmatrix x4: 4 8x8 b16 tiles; tile k taken from addresses of threads 8k..8k+7.
__device__ __forceinline__ void ldsm4(uint32_t* d, uint32_t addr) {
    asm volatile(
        "ldmatrix.sync.aligned.m8n8.x4.shared.b16 {%0,%1,%2,%3}, [%4];"
        : "=r"(d[0]), "=r"(d[1]), "=r"(d[2]), "=r"(d[3]) : "r"(addr));
}

// XOR-swizzled float index: row-major [s][64], 16B chunks XORed by (s&7)
__device__ __forceinline__ int swz(int s, int d) {
    return s * 64 + ((((d >> 2) ^ (s & 7)) << 2) | (d & 3));
}

// ---------------------------------------------------------------------------
// Round-to-tf32 copy kernel (n divisible by 4)
// ---------------------------------------------------------------------------
__global__ __launch_bounds__(256) void round_tf32_k(const float* __restrict__ in,
                                                    float* __restrict__ out, int n4)
{
    int i = blockIdx.x * 256 + threadIdx.x;
    if (i < n4) {
        float4 v = ((const float4*)in)[i];
        v.x = __uint_as_float(cvt_tf32(v.x));
        v.y = __uint_as_float(cvt_tf32(v.y));
        v.z = __uint_as_float(cvt_tf32(v.z));
        v.w = __uint_as_float(cvt_tf32(v.w));
        ((float4*)out)[i] = v;
    }
}

// ---------------------------------------------------------------------------
// tf32 mma.sync GEMM: C[m][n] = sum_k A[m*K+k] * W[n*K+k]
// Inputs must already be tf32-rounded.
// BM=128, BN=128, BK=32, 128 threads (4 warps, 2x2, warp tile 64x64).
// Fragment loads via ldmatrix.x4.b16 (tf32 fragment == b16 tile quad).
// ---------------------------------------------------------------------------
#define GEMM_SMEM_BYTES (4 * 16384)

__global__ __launch_bounds__(128, 2)
void gemm_tf32(const float* __restrict__ A, const float* __restrict__ W,
               float* __restrict__ C, int M, int N, int K)
{
    extern __shared__ float sm[];
    const uint32_t sb = smem_u32(sm);

    const int tid = threadIdx.x;
    const int wid = tid >> 5;
    const int lane = tid & 31;
    const int g = lane >> 2;
    const int r = lane & 3;
    const int wm = wid & 1;
    const int wn = wid >> 1;
    const int bm = blockIdx.y * 128;
    const int bn = blockIdx.x * 128;
    const int nK = K >> 5;

    const int c4 = tid & 7;
    const int r0 = tid >> 3;          // 0..15
    const float* Ag = A + (size_t)(bm + r0) * K + c4 * 4;
    const float* Wg = W + (size_t)(bn + r0) * K + c4 * 4;

    // ldmatrix per-thread addresses (buffer 0): thread -> (row, chunk) of its tile
    const int q8 = lane & 7;
    const int sel = lane >> 3;        // 0..3
    uint32_t aaddr[4], baddr[4];
#pragma unroll
    for (int mi = 0; mi < 4; ++mi) {
        int row = wm * 64 + mi * 16 + q8 + ((sel & 1) << 3);
        aaddr[mi] = sb + row * 128 + ((((uint32_t)(sel >> 1) ^ (row & 7)) << 4));
    }
#pragma unroll
    for (int p = 0; p < 4; ++p) {
        int row = wn * 64 + p * 16 + q8 + ((sel & 1) << 3);
        baddr[p] = sb + 32768 + row * 128 + ((((uint32_t)(sel >> 1) ^ (row & 7)) << 4));
    }

    float acc[4][8][4];
#pragma unroll
    for (int mi = 0; mi < 4; ++mi)
#pragma unroll
        for (int ni = 0; ni < 8; ++ni)
#pragma unroll
            for (int j = 0; j < 4; ++j) acc[mi][ni][j] = 0.0f;

    {
        uint32_t sa = sb;
        uint32_t sw = sb + 32768;
#pragma unroll
        for (int i = 0; i < 8; ++i) {
            int row = r0 + i * 16;
            uint32_t off = row * 128 + ((c4 ^ (row & 7)) << 4);
            asm volatile("cp.async.cg.shared.global [%0], [%1], 16;"
                         :: "r"(sa + off), "l"(Ag + (size_t)i * 16 * K) : "memory");
            asm volatile("cp.async.cg.shared.global [%0], [%1], 16;"
                         :: "r"(sw + off), "l"(Wg + (size_t)i * 16 * K) : "memory");
        }
        asm volatile("cp.async.commit_group;" ::: "memory");
    }

    for (int kt = 0; kt < nK; ++kt) {
        if (kt + 1 < nK) {
            int nb = (kt + 1) & 1;
            uint32_t sa = sb + nb * 16384;
            uint32_t sw = sb + 32768 + nb * 16384;
            const float* ag = Ag + (size_t)(kt + 1) * 32;
            const float* wg = Wg + (size_t)(kt + 1) * 32;
#pragma unroll
            for (int i = 0; i < 8; ++i) {
                int row = r0 + i * 16;
                uint32_t off = row * 128 + ((c4 ^ (row & 7)) << 4);
                asm volatile("cp.async.cg.shared.global [%0], [%1], 16;"
                             :: "r"(sa + off), "l"(ag + (size_t)i * 16 * K) : "memory");
                asm volatile("cp.async.cg.shared.global [%0], [%1], 16;"
                             :: "r"(sw + off), "l"(wg + (size_t)i * 16 * K) : "memory");
            }
            asm volatile("cp.async.commit_group;" ::: "memory");
            asm volatile("cp.async.wait_group 1;" ::: "memory");
        } else {
            asm volatile("cp.async.wait_group 0;" ::: "memory");
        }
        __syncthreads();

        const uint32_t bo = (uint32_t)(kt & 1) << 14;   // buffer offset 16384

#pragma unroll
        for (int ks = 0; ks < 4; ++ks) {
            const uint32_t xk = (uint32_t)ks << 5;

            uint32_t af[4][4];
#pragma unroll
            for (int mi = 0; mi < 4; ++mi)
                ldsm4(af[mi], (aaddr[mi] + bo) ^ xk);

            uint32_t bf[8][2];
#pragma unroll
            for (int p = 0; p < 4; ++p) {
                uint32_t bb[4];
                ldsm4(bb, (baddr[p] + bo) ^ xk);
                bf[2 * p][0] = bb[0];     bf[2 * p][1] = bb[2];
                bf[2 * p + 1][0] = bb[1]; bf[2 * p + 1][1] = bb[3];
            }
#pragma unroll
            for (int mi = 0; mi < 4; ++mi)
#pragma unroll
                for (int ni = 0; ni < 8; ++ni)
                    mma_tf32(acc[mi][ni], af[mi], bf[ni]);
        }
        __syncthreads();
    }

#pragma unroll
    for (int mi = 0; mi < 4; ++mi) {
        int r1 = bm + wm * 64 + mi * 16 + g;
#pragma unroll
        for (int ni = 0; ni < 8; ++ni) {
            int cc = bn + wn * 64 + ni * 8 + r * 2;
            *(float2*)(C + (size_t)r1 * N + cc) =
                make_float2(acc[mi][ni][0], acc[mi][ni][1]);
            *(float2*)(C + (size_t)(r1 + 8) * N + cc) =
                make_float2(acc[mi][ni][2], acc[mi][ni][3]);
        }
    }
}

// ---------------------------------------------------------------------------
// RoPE + scatter, outputs tf32-rounded q/k/v in [B][H][T][D]
// ---------------------------------------------------------------------------
__global__ __launch_bounds__(256) void rope_scatter()
{
    int gid = blockIdx.x * 256 + threadIdx.x;
    int i = gid & 31;
    int h = (gid >> 5) % Hq;
    int bt = gid / (32 * Hq);
    int t = bt & (Tq - 1);
    int b = bt >> 10;

    const float* row = g_qkv + (size_t)bt * (3 * Cq);

    float ang = (float)t * exp2f(-(float)i * (13.2877123795494936f / 32.0f));
    float s, c;
    sincosf(ang, &s, &c);

    int base = h * 64;
    size_t dst = ((size_t)(b * Hq + h) * Tq + t) * 64;

    {
        float x1 = row[base + i];
        float x2 = row[base + i + 32];
        g_q[dst + i]      = __uint_as_float(cvt_tf32(x1 * c + x2 * s));
        g_q[dst + i + 32] = __uint_as_float(cvt_tf32(-x1 * s + x2 * c));
    }
    {
        float x1 = row[Cq + base + i];
        float x2 = row[Cq + base + i + 32];
        g_k[dst + i]      = __uint_as_float(cvt_tf32(x1 * c + x2 * s));
        g_k[dst + i + 32] = __uint_as_float(cvt_tf32(-x1 * s + x2 * c));
    }
    {
        g_v[dst + i]      = __uint_as_float(cvt_tf32(row[2 * Cq + base + i]));
        g_v[dst + i + 32] = __uint_as_float(cvt_tf32(row[2 * Cq + base + i + 32]));
    }
}

// ---------------------------------------------------------------------------
// Tensor-core flash attention (causal), tf32 mma.sync + ldmatrix.
// Block = (qb128, h, b): 128 q rows, 256 threads (8 warps x 16 rows).
// kv tiles of 64 keys, double-buffered cp.async.
// smem floats: Ks[2][4096] swizzled | Vs[2][4608] stride 72 | Ps[8192] swizzled
// ---------------------------------------------------------------------------
#define ATTN2_SMEM_BYTES 102400

__device__ __forceinline__ void load_kv_tile(uint32_t ksm, uint32_t vsm,
                                             const float* kt, const float* vt,
                                             int tid)
{
    int s = tid >> 2, c0 = tid & 3;
#pragma unroll
    for (int i = 0; i < 4; ++i) {
        int c = c0 + i * 4;
        asm volatile("cp.async.cg.shared.global [%0], [%1], 16;"
                     :: "r"(ksm + s * 256 + ((c ^ (s & 7)) << 4)),
                        "l"(kt + s * 64 + c * 4) : "memory");
        asm volatile("cp.async.cg.shared.global [%0], [%1], 16;"
                     :: "r"(vsm + s * 288 + (c << 4)),
                        "l"(vt + s * 64 + c * 4) : "memory");
    }
    asm volatile("cp.async.commit_group;" ::: "memory");
}

__global__ __launch_bounds__(256) void attn_mma(const float* __restrict__ gq,
                                                const float* __restrict__ gk,
                                                const float* __restrict__ gv,
                                                float* __restrict__ gatt)
{
    extern __shared__ float sm2[];
    float* Ks = sm2;                // [2][4096]
    float* Vs = sm2 + 8192;         // [2][4608], stride 72
    float* Ps = sm2 + 17408;        // [8192] (Q staging, then per-warp P)

    const int tid = threadIdx.x;
    const int wid = tid >> 5;
    const int lane = tid & 31;
    const int g = lane >> 2;
    const int r = lane & 3;
    const int qb = (gridDim.x - 1) - blockIdx.x;   // heavy tiles first
    const int h = blockIdx.y;
    const int b = blockIdx.z;

    const float* qp = gq + ((size_t)(b * Hq + h) * Tq + qb * 128) * 64;
    const float* kp = gk + (size_t)(b * Hq + h) * Tq * 64;
    const float* vp = gv + (size_t)(b * Hq + h) * Tq * 64;
    const int nst = 2 * qb + 2;

    const uint32_t ksm = smem_u32(Ks);
    const uint32_t vsm = smem_u32(Vs);
    const uint32_t psm = smem_u32(Ps);

    // prefetch kv tile 0
    load_kv_tile(ksm, vsm, kp, vp, tid);

    // stage Q (128x64) into Ps with swizzle, then lift fragments via ldmatrix
#pragma unroll
    for (int i = 0; i < 8; ++i) {
        int idx = tid + i * 256;
        int s = idx >> 4, c = idx & 15;
        float4 v = *(const float4*)(qp + s * 64 + c * 4);
        *(float4*)(Ps + s * 64 + ((c ^ (s & 7)) << 2)) = v;
    }
    __syncthreads();

    const int q8 = lane & 7;
    const int sel = lane >> 3;      // 0..3

    uint32_t qf[8][4];
    {
        int row = wid * 16 + q8 + ((sel & 1) << 3);
        uint32_t qaddr = psm + row * 256 + ((((uint32_t)(sel >> 1) ^ (row & 7)) << 4));
#pragma unroll
        for (int ks = 0; ks < 8; ++ks)
            ldsm4(qf[ks], qaddr ^ ((uint32_t)ks << 5));
    }
    __syncthreads();

    // ldmatrix bases: K fragments (nt-pairs) and P fragments (A-type)
    uint32_t kaddr[4];
#pragma unroll
    for (int p = 0; p < 4; ++p) {
        int row = p * 16 + q8 + ((sel & 1) << 3);
        kaddr[p] = row * 256 + ((((uint32_t)(sel >> 1) ^ (row & 7)) << 4));
    }
    uint32_t paddr;
    {
        int row = q8 + ((sel & 1) << 3);
        paddr = psm + wid * 4096 + row * 256 +
                ((((uint32_t)(sel >> 1) ^ (row & 7)) << 4));
    }
    // P stores (float2 at d0 = nt*8 + 2r): idx = ipw ^ (nt*8)
    const uint32_t pw_lo = (((r >> 1) ^ (g & 7)) << 2) + ((2 * r) & 3);
    const uint32_t ipw0 = g * 64 + pw_lo;
    const uint32_t ipw1 = (g + 8) * 64 + pw_lo;

    float m0 = -1e30f, m1 = -1e30f, l0 = 0.0f, l1 = 0.0f;
    float o[8][4];
#pragma unroll
    for (int dt = 0; dt < 8; ++dt)
#pragma unroll
        for (int j = 0; j < 4; ++j) o[dt][j] = 0.0f;

    float* Pw = Ps + wid * 1024;
    const int qlo = qb * 128 + wid * 16;
    const int qr0 = qlo + g;

    for (int st = 0; st < nst; ++st) {
        if (st + 1 < nst) {
            load_kv_tile(ksm + ((st + 1) & 1) * 16384, vsm + ((st + 1) & 1) * 18432,
                         kp + (size_t)(st + 1) * 4096, vp + (size_t)(st + 1) * 4096, tid);
            asm volatile("cp.async.wait_group 1;" ::: "memory");
        } else {
            asm volatile("cp.async.wait_group 0;" ::: "memory");
        }
        __syncthreads();

        const int collo = st * 64;
        if (collo <= qlo + 15) {                 // warp not fully masked
            const uint32_t kbase = ksm + (st & 1) * 16384;
            const float* vb = Vs + (st & 1) * 4608;

            // S = Q K^T
            float s4[8][4];
#pragma unroll
            for (int nt = 0; nt < 8; ++nt)
#pragma unroll
                for (int j = 0; j < 4; ++j) s4[nt][j] = 0.0f;
#pragma unroll
            for (int ks = 0; ks < 8; ++ks) {
                const uint32_t xk = (uint32_t)ks << 5;
#pragma unroll
                for (int p = 0; p < 4; ++p) {
                    uint32_t bb[4];
                    ldsm4(bb, (kbase + kaddr[p]) ^ xk);
                    uint32_t bk0[2] = {bb[0], bb[2]};
                    uint32_t bk1[2] = {bb[1], bb[3]};
                    mma_tf32(s4[2 * p], qf[ks], bk0);
                    mma_tf32(s4[2 * p + 1], qf[ks], bk1);
                }
            }

            const bool diag = (collo + 63 > qlo);
#pragma unroll
            for (int nt = 0; nt < 8; ++nt) {
                s4[nt][0] *= 0.125f; s4[nt][1] *= 0.125f;
                s4[nt][2] *= 0.125f; s4[nt][3] *= 0.125f;
                if (diag) {
                    int c0 = collo + nt * 8 + 2 * r;
                    if (c0     > qr0)     s4[nt][0] = -1e30f;
                    if (c0 + 1 > qr0)     s4[nt][1] = -1e30f;
                    if (c0     > qr0 + 8) s4[nt][2] = -1e30f;
                    if (c0 + 1 > qr0 + 8) s4[nt][3] = -1e30f;
                }
            }

            // online softmax (rows qr0 and qr0+8)
            float mx0 = -1e30f, mx1 = -1e30f;
#pragma unroll
            for (int nt = 0; nt < 8; ++nt) {
                mx0 = fmaxf(mx0, fmaxf(s4[nt][0], s4[nt][1]));
                mx1 = fmaxf(mx1, fmaxf(s4[nt][2], s4[nt][3]));
            }
            mx0 = fmaxf(mx0, __shfl_xor_sync(0xffffffffu, mx0, 1));
            mx0 = fmaxf(mx0, __shfl_xor_sync(0xffffffffu, mx0, 2));
            mx1 = fmaxf(mx1, __shfl_xor_sync(0xffffffffu, mx1, 1));
            mx1 = fmaxf(mx1, __shfl_xor_sync(0xffffffffu, mx1, 2));

            float mn0 = fmaxf(m0, mx0), mn1 = fmaxf(m1, mx1);
            float cr0 = __expf(m0 - mn0), cr1 = __expf(m1 - mn1);
            m0 = mn0; m1 = mn1;

            float sum0 = 0.0f, sum1 = 0.0f;
#pragma unroll
            for (int nt = 0; nt < 8; ++nt) {
                float p00 = __expf(s4[nt][0] - m0);
                float p01 = __expf(s4[nt][1] - m0);
                float p10 = __expf(s4[nt][2] - m1);
                float p11 = __expf(s4[nt][3] - m1);
                sum0 += p00 + p01;
                sum1 += p10 + p11;
                *(float2*)(Pw + (ipw0 ^ (uint32_t)(nt * 8))) =
                    make_float2(__uint_as_float(cvt_tf32(p00)),
                                __uint_as_float(cvt_tf32(p01)));
                *(float2*)(Pw + (ipw1 ^ (uint32_t)(nt * 8))) =
                    make_float2(__uint_as_float(cvt_tf32(p10)),
                                __uint_as_float(cvt_tf32(p11)));
            }
            sum0 += __shfl_xor_sync(0xffffffffu, sum0, 1);
            sum0 += __shfl_xor_sync(0xffffffffu, sum0, 2);
            sum1 += __shfl_xor_sync(0xffffffffu, sum1, 1);
            sum1 += __shfl_xor_sync(0xffffffffu, sum1, 2);
            l0 = l0 * cr0 + sum0;
            l1 = l1 * cr1 + sum1;

#pragma unroll
            for (int dt = 0; dt < 8; ++dt) {
                o[dt][0] *= cr0; o[dt][1] *= cr0;
                o[dt][2] *= cr1; o[dt][3] *= cr1;
            }
            __syncwarp();

            // O += P V
#pragma unroll
            for (int ks = 0; ks < 8; ++ks) {
                uint32_t pa[4];
                ldsm4(pa, paddr ^ ((uint32_t)ks << 5));
#pragma unroll
                for (int dt = 0; dt < 8; ++dt) {
                    uint32_t bv[2];
                    bv[0] = __float_as_uint(vb[(ks * 8 + r) * 72 + dt * 8 + g]);
                    bv[1] = __float_as_uint(vb[(ks * 8 + r + 4) * 72 + dt * 8 + g]);
                    mma_tf32(o[dt], pa, bv);
                }
            }
        }
        __syncthreads();   // protect K/V buffers & Ps before next iteration
    }

    // finalize: write tf32-rounded output (A operand of proj GEMM)
    float li0 = 1.0f / l0, li1 = 1.0f / l1;
    int t0 = qb * 128 + wid * 16 + g;
    float* ob = gatt + ((size_t)b * Tq + t0) * Cq + h * 64;
#pragma unroll
    for (int dt = 0; dt < 8; ++dt) {
        int cc = dt * 8 + 2 * r;
        *(float2*)(ob + cc) =
            make_float2(__uint_as_float(cvt_tf32(o[dt][0] * li0)),
                        __uint_as_float(cvt_tf32(o[dt][1] * li0)));
        *(float2*)(ob + 8 * Cq + cc) =
            make_float2(__uint_as_float(cvt_tf32(o[dt][2] * li1)),
                        __uint_as_float(cvt_tf32(o[dt][3] * li1)));
    }
}

// ---------------------------------------------------------------------------
// Launch
// ---------------------------------------------------------------------------
extern "C" void kernel_launch(void* const* d_in, const int* in_sizes, int n_in,
                              void* d_out, int out_size)
{
    const float* x      = (const float*)d_in[0];
    const float* w_qkv  = (const float*)d_in[1];
    const float* w_proj = (const float*)d_in[2];
    float* out = (float*)d_out;

    float *qkv, *q, *k, *v, *att, *xr, *wqr, *wpr;
    cudaGetSymbolAddress((void**)&qkv, g_qkv);
    cudaGetSymbolAddress((void**)&q, g_q);
    cudaGetSymbolAddress((void**)&k, g_k);
    cudaGetSymbolAddress((void**)&v, g_v);
    cudaGetSymbolAddress((void**)&att, g_att);
    cudaGetSymbolAddress((void**)&xr, g_xr);
    cudaGetSymbolAddress((void**)&wqr, g_wqkv_r);
    cudaGetSymbolAddress((void**)&wpr, g_wproj_r);

    const int M = Bq * Tq;  // 8192

    cudaFuncSetAttribute(gemm_tf32, cudaFuncAttributeMaxDynamicSharedMemorySize,
                         GEMM_SMEM_BYTES);
    cudaFuncSetAttribute(attn_mma, cudaFuncAttributeMaxDynamicSharedMemorySize,
                         ATTN2_SMEM_BYTES);

    // 0. tf32-round GEMM operands
    round_tf32_k<<<(M * Cq / 4 + 255) / 256, 256>>>(x, xr, M * Cq / 4);
    round_tf32_k<<<(3 * Cq * Cq / 4 + 255) / 256, 256>>>(w_qkv, wqr, 3 * Cq * Cq / 4);
    round_tf32_k<<<(Cq * Cq / 4 + 255) / 256, 256>>>(w_proj, wpr, Cq * Cq / 4);

    // 1. qkv = x @ w_qkv^T
    gemm_tf32<<<dim3((3 * Cq) / 128, M / 128), 128, GEMM_SMEM_BYTES>>>(
        xr, wqr, qkv, M, 3 * Cq, Cq);

    // 2. RoPE + scatter (tf32-rounded q/k/v)
    rope_scatter<<<(Bq * Tq * Hq * 32) / 256, 256>>>();

    // 3. Tensor-core causal flash attention
    attn_mma<<<dim3(Tq / 128, Hq, Bq), 256, ATTN2_SMEM_BYTES>>>(q, k, v, att);

    // 4. out = att @ w_proj^T
    gemm_tf32<<<dim3(Cq / 128, M / 128), 128, GEMM_SMEM_BYTES>>>(
        att, wpr, out, M, Cq, Cq);
}

// round 15
// speedup vs baseline: 1.0087x; 1.0087x over previous
#include <cuda_runtime.h>
#include <math.h>
#include <cstdint>

// Problem dims
#define Bq 8
#define Tq 1024
#define Cq 768
#define Hq 12
#define Dq 64

// Scratch (device globals: allocation-free rule)
__device__ float g_qkv[(size_t)Bq * Tq * 3 * Cq];   // [B*T][2304]
__device__ float g_q[(size_t)Bq * Hq * Tq * Dq];    // [B][H][T][D] (tf32-rounded)
__device__ float g_k[(size_t)Bq * Hq * Tq * Dq];
__device__ float g_v[(size_t)Bq * Hq * Tq * Dq];
__device__ float g_att[(size_t)Bq * Tq * Cq];       // [B][T][C]   (tf32-rounded)
__device__ float g_xr[(size_t)Bq * Tq * Cq];        // rounded x
__device__ float g_wqkv_r[(size_t)3 * Cq * Cq];     // rounded w_qkv
__device__ float g_wproj_r[(size_t)Cq * Cq];        // rounded w_proj

// ---------------------------------------------------------------------------
// Helpers
// ---------------------------------------------------------------------------
__device__ __forceinline__ uint32_t smem_u32(const void* p) {
    uint32_t a;
    asm("{ .reg .u64 t; cvta.to.shared.u64 t, %1; cvt.u32.u64 %0, t; }"
        : "=r"(a) : "l"(p));
    return a;
}

__device__ __forceinline__ uint32_t cvt_tf32(float v) {
    uint32_t u;
    asm("cvt.rna.tf32.f32 %0, %1;" : "=r"(u) : "f"(v));
    return u;
}

__device__ __forceinline__ void mma_tf32(float* d, const uint32_t* a,
                                         const uint32_t* b) {
    asm volatile(
        "mma.sync.aligned.m16n8k8.row.col.f32.tf32.tf32.f32 "
        "{%0,%1,%2,%3}, {%4,%5,%6,%7}, {%8,%9}, {%0,%1,%2,%3};"
        : "+f"(d[0]), "+f"(d[1]), "+f"(d[2]), "+f"(d[3])
        : "r"(a[0]), "r"(a[1]), "r"(a[2]), "r"(a[3]), "r"(b[0]), "r"(b[1]));
}

// XOR-swizzled float index: row-major [s][64], 16B chunks XORed by (s&7)
__device__ __forceinline__ int swz(int s, int d) {
    return s * 64 + ((((d >> 2) ^ (s & 7)) << 2) | (d & 3));
}

__device__ __forceinline__ float lds_sw(const float* base, int row, int k) {
    return base[row * 32 + (((k >> 2) ^ (row & 7)) << 2) + (k & 3)];
}

// ---------------------------------------------------------------------------
// Round-to-tf32 copy kernel (n divisible by 4)
// ---------------------------------------------------------------------------
__global__ __launch_bounds__(256) void round_tf32_k(const float* __restrict__ in,
                                                    float* __restrict__ out, int n4)
{
    int i = blockIdx.x * 256 + threadIdx.x;
    if (i < n4) {
        float4 v = ((const float4*)in)[i];
        v.x = __uint_as_float(cvt_tf32(v.x));
        v.y = __uint_as_float(cvt_tf32(v.y));
        v.z = __uint_as_float(cvt_tf32(v.z));
        v.w = __uint_as_float(cvt_tf32(v.w));
        ((float4*)out)[i] = v;
    }
}

// ---------------------------------------------------------------------------
// tf32 mma.sync GEMM: C[m][n] = sum_k A[m*K+k] * W[n*K+k]   (R13 version)
// BM=128, BN=128, BK=32, 128 threads (4 warps, 2x2, warp tile 64x64).
// ---------------------------------------------------------------------------
#define GEMM_SMEM_BYTES (4 * 16384)

__global__ __launch_bounds__(128, 2)
void gemm_tf32(const float* __restrict__ A, const float* __restrict__ W,
               float* __restrict__ C, int M, int N, int K)
{
    extern __shared__ float sm[];
    const uint32_t sb = smem_u32(sm);

    const int tid = threadIdx.x;
    const int wid = tid >> 5;
    const int lane = tid & 31;
    const int g = lane >> 2;
    const int r = lane & 3;
    const int wm = wid & 1;
    const int wn = wid >> 1;
    const int bm = blockIdx.y * 128;
    const int bn = blockIdx.x * 128;
    const int nK = K >> 5;

    const int c4 = tid & 7;
    const int r0 = tid >> 3;          // 0..15
    const float* Ag = A + (size_t)(bm + r0) * K + c4 * 4;
    const float* Wg = W + (size_t)(bn + r0) * K + c4 * 4;

    uint32_t ia0[4][2], ib0[8];
#pragma unroll
    for (int mi = 0; mi < 4; ++mi) {
        int r1 = wm * 64 + mi * 16 + g;
        uint32_t lo = ((r1 & 7) << 2) + r;
        ia0[mi][0] = r1 * 32 + lo;
        ia0[mi][1] = (r1 + 8) * 32 + lo;
    }
#pragma unroll
    for (int ni = 0; ni < 8; ++ni) {
        int n = wn * 64 + ni * 8 + g;
        ib0[ni] = n * 32 + ((n & 7) << 2) + r;
    }

    float acc[4][8][4];
#pragma unroll
    for (int mi = 0; mi < 4; ++mi)
#pragma unroll
        for (int ni = 0; ni < 8; ++ni)
#pragma unroll
            for (int j = 0; j < 4; ++j) acc[mi][ni][j] = 0.0f;

    {
        uint32_t sa = sb;
        uint32_t sw = sb + 32768;
#pragma unroll
        for (int i = 0; i < 8; ++i) {
            int row = r0 + i * 16;
            uint32_t off = row * 128 + ((c4 ^ (row & 7)) << 4);
            asm volatile("cp.async.cg.shared.global [%0], [%1], 16;"
                         :: "r"(sa + off), "l"(Ag + (size_t)i * 16 * K) : "memory");
            asm volatile("cp.async.cg.shared.global [%0], [%1], 16;"
                         :: "r"(sw + off), "l"(Wg + (size_t)i * 16 * K) : "memory");
        }
        asm volatile("cp.async.commit_group;" ::: "memory");
    }

    for (int kt = 0; kt < nK; ++kt) {
        if (kt + 1 < nK) {
            int nb = (kt + 1) & 1;
            uint32_t sa = sb + nb * 16384;
            uint32_t sw = sb + 32768 + nb * 16384;
            const float* ag = Ag + (size_t)(kt + 1) * 32;
            const float* wg = Wg + (size_t)(kt + 1) * 32;
#pragma unroll
            for (int i = 0; i < 8; ++i) {
                int row = r0 + i * 16;
                uint32_t off = row * 128 + ((c4 ^ (row & 7)) << 4);
                asm volatile("cp.async.cg.shared.global [%0], [%1], 16;"
                             :: "r"(sa + off), "l"(ag + (size_t)i * 16 * K) : "memory");
                asm volatile("cp.async.cg.shared.global [%0], [%1], 16;"
                             :: "r"(sw + off), "l"(wg + (size_t)i * 16 * K) : "memory");
            }
            asm volatile("cp.async.commit_group;" ::: "memory");
            asm volatile("cp.async.wait_group 1;" ::: "memory");
        } else {
            asm volatile("cp.async.wait_group 0;" ::: "memory");
        }
        __syncthreads();

        const int buf = kt & 1;
        const float* a = sm + buf * 4096;
        const float* b = sm + 8192 + buf * 4096;

#pragma unroll
        for (int ks = 0; ks < 4; ++ks) {
            const uint32_t x0 = ks * 8, x1 = ks * 8 + 4;

            uint32_t af[4][4];
#pragma unroll
            for (int mi = 0; mi < 4; ++mi) {
                af[mi][0] = __float_as_uint(a[ia0[mi][0] ^ x0]);
                af[mi][1] = __float_as_uint(a[ia0[mi][1] ^ x0]);
                af[mi][2] = __float_as_uint(a[ia0[mi][0] ^ x1]);
                af[mi][3] = __float_as_uint(a[ia0[mi][1] ^ x1]);
            }
            uint32_t bf[8][2];
#pragma unroll
            for (int ni = 0; ni < 8; ++ni) {
                bf[ni][0] = __float_as_uint(b[ib0[ni] ^ x0]);
                bf[ni][1] = __float_as_uint(b[ib0[ni] ^ x1]);
            }
#pragma unroll
            for (int mi = 0; mi < 4; ++mi)
#pragma unroll
                for (int ni = 0; ni < 8; ++ni)
                    mma_tf32(acc[mi][ni], af[mi], bf[ni]);
        }
        __syncthreads();
    }

#pragma unroll
    for (int mi = 0; mi < 4; ++mi) {
        int r1 = bm + wm * 64 + mi * 16 + g;
#pragma unroll
        for (int ni = 0; ni < 8; ++ni) {
            int cc = bn + wn * 64 + ni * 8 + r * 2;
            *(float2*)(C + (size_t)r1 * N + cc) =
                make_float2(acc[mi][ni][0], acc[mi][ni][1]);
            *(float2*)(C + (size_t)(r1 + 8) * N + cc) =
                make_float2(acc[mi][ni][2], acc[mi][ni][3]);
        }
    }
}

// ---------------------------------------------------------------------------
// RoPE + scatter, outputs tf32-rounded q/k/v in [B][H][T][D]
// ---------------------------------------------------------------------------
__global__ __launch_bounds__(256) void rope_scatter()
{
    int gid = blockIdx.x * 256 + threadIdx.x;
    int i = gid & 31;
    int h = (gid >> 5) % Hq;
    int bt = gid / (32 * Hq);
    int t = bt & (Tq - 1);
    int b = bt >> 10;

    const float* row = g_qkv + (size_t)bt * (3 * Cq);

    float ang = (float)t * exp2f(-(float)i * (13.2877123795494936f / 32.0f));
    float s, c;
    sincosf(ang, &s, &c);

    int base = h * 64;
    size_t dst = ((size_t)(b * Hq + h) * Tq + t) * 64;

    {
        float x1 = row[base + i];
        float x2 = row[base + i + 32];
        g_q[dst + i]      = __uint_as_float(cvt_tf32(x1 * c + x2 * s));
        g_q[dst + i + 32] = __uint_as_float(cvt_tf32(-x1 * s + x2 * c));
    }
    {
        float x1 = row[Cq + base + i];
        float x2 = row[Cq + base + i + 32];
        g_k[dst + i]      = __uint_as_float(cvt_tf32(x1 * c + x2 * s));
        g_k[dst + i + 32] = __uint_as_float(cvt_tf32(-x1 * s + x2 * c));
    }
    {
        g_v[dst + i]      = __uint_as_float(cvt_tf32(row[2 * Cq + base + i]));
        g_v[dst + i + 32] = __uint_as_float(cvt_tf32(row[2 * Cq + base + i + 32]));
    }
}

// ---------------------------------------------------------------------------
// Tensor-core flash attention (causal), tf32 mma.sync.
// Block = (qb256, h, b): 256 q rows, 256 threads, 8 warps x 32 q-rows.
// Each warp: 2 m-frags (16 rows) sharing every K/V fragment load.
// kv tiles of 64 keys, double-buffered cp.async.
// smem floats: Ks[2][4096] | Vs[2][4608] stride 72 | Ps 8 x 2048 (Q stage / P)
// ---------------------------------------------------------------------------
#define ATTN2_SMEM_BYTES ((17408 + 8 * 2048) * 4)   // 135168

__device__ __forceinline__ void load_kv_tile(uint32_t ksm, uint32_t vsm,
                                             const float* kt, const float* vt,
                                             int tid)
{
    int s = tid >> 2, c0 = tid & 3;
#pragma unroll
    for (int i = 0; i < 4; ++i) {
        int c = c0 + i * 4;
        asm volatile("cp.async.cg.shared.global [%0], [%1], 16;"
                     :: "r"(ksm + s * 256 + ((c ^ (s & 7)) << 4)),
                        "l"(kt + s * 64 + c * 4) : "memory");
        asm volatile("cp.async.cg.shared.global [%0], [%1], 16;"
                     :: "r"(vsm + s * 288 + (c << 4)),
                        "l"(vt + s * 64 + c * 4) : "memory");
    }
    asm volatile("cp.async.commit_group;" ::: "memory");
}

__global__ __launch_bounds__(256) void attn_mma(const float* __restrict__ gq,
                                                const float* __restrict__ gk,
                                                const float* __restrict__ gv,
                                                float* __restrict__ gatt)
{
    extern __shared__ float sm2[];
    float* Ks = sm2;                // [2][4096]
    float* Vs = sm2 + 8192;         // [2][4608], stride 72
    float* Ps = sm2 + 17408;        // 8 warps x 2048 (Q stage, then P)

    const int tid = threadIdx.x;
    const int wid = tid >> 5;
    const int lane = tid & 31;
    const int g = lane >> 2;
    const int r = lane & 3;
    const int qb = (gridDim.x - 1) - blockIdx.x;   // heavy tiles first
    const int h = blockIdx.y;
    const int b = blockIdx.z;

    const float* qp = gq + ((size_t)(b * Hq + h) * Tq + qb * 256) * 64;
    const float* kp = gk + (size_t)(b * Hq + h) * Tq * 64;
    const float* vp = gv + (size_t)(b * Hq + h) * Tq * 64;
    const int nst = 4 * qb + 4;

    const uint32_t ksm = smem_u32(Ks);
    const uint32_t vsm = smem_u32(Vs);

    // prefetch kv tile 0
    load_kv_tile(ksm, vsm, kp, vp, tid);

    float* Pw = Ps + wid * 2048;     // this warp's 32x64 region

    // Warp-private Q stage: rows wid*32..wid*32+31 -> Pw (swizzled), then lift.
#pragma unroll
    for (int i = 0; i < 16; ++i) {
        int idx = lane + i * 32;
        int srow = idx >> 4, c = idx & 15;
        float4 v = *(const float4*)(qp + (wid * 32 + srow) * 64 + c * 4);
        *(float4*)(Pw + srow * 64 + ((c ^ (srow & 7)) << 2)) = v;
    }
    __syncwarp();
    uint32_t qf[2][8][4];
#pragma unroll
    for (int mf = 0; mf < 2; ++mf) {
        int q0 = mf * 16 + g;
#pragma unroll
        for (int ks = 0; ks < 8; ++ks) {
            qf[mf][ks][0] = __float_as_uint(Pw[swz(q0, ks * 8 + r)]);
            qf[mf][ks][1] = __float_as_uint(Pw[swz(q0 + 8, ks * 8 + r)]);
            qf[mf][ks][2] = __float_as_uint(Pw[swz(q0, ks * 8 + r + 4)]);
            qf[mf][ks][3] = __float_as_uint(Pw[swz(q0 + 8, ks * 8 + r + 4)]);
        }
    }
    __syncwarp();

    // K fragment bases (rows nt*8+g of 64-float swizzled rows)
    uint32_t ikb[8];
#pragma unroll
    for (int nt = 0; nt < 8; ++nt) {
        int row = nt * 8 + g;
        ikb[nt] = row * 64 + ((row & 7) << 2) + r;
    }
    // P fragment load bases per mf (rows mf*16+g, mf*16+8+g); (row&7)==g
    uint32_t ipa[2][2];
    // P store bases per mf (float2 at col 2r)
    const uint32_t pw_lo = (((r >> 1) ^ (g & 7)) << 2) + ((2 * r) & 3);
    uint32_t ipw[2][2];
#pragma unroll
    for (int mf = 0; mf < 2; ++mf) {
        int row0 = mf * 16 + g;
        ipa[mf][0] = row0 * 64 + ((g & 7) << 2) + r;
        ipa[mf][1] = (row0 + 8) * 64 + ((g & 7) << 2) + r;
        ipw[mf][0] = row0 * 64 + pw_lo;
        ipw[mf][1] = (row0 + 8) * 64 + pw_lo;
    }

    float mM[2][2], lL[2][2];
#pragma unroll
    for (int mf = 0; mf < 2; ++mf) {
        mM[mf][0] = -1e30f; mM[mf][1] = -1e30f;
        lL[mf][0] = 0.0f;   lL[mf][1] = 0.0f;
    }
    float o[2][8][4];
#pragma unroll
    for (int mf = 0; mf < 2; ++mf)
#pragma unroll
        for (int dt = 0; dt < 8; ++dt)
#pragma unroll
            for (int j = 0; j < 4; ++j) o[mf][dt][j] = 0.0f;

    const int qlo = qb * 256 + wid * 32;

    for (int st = 0; st < nst; ++st) {
        if (st + 1 < nst) {
            load_kv_tile(ksm + ((st + 1) & 1) * 16384, vsm + ((st + 1) & 1) * 18432,
                         kp + (size_t)(st + 1) * 4096, vp + (size_t)(st + 1) * 4096, tid);
            asm volatile("cp.async.wait_group 1;" ::: "memory");
        } else {
            asm volatile("cp.async.wait_group 0;" ::: "memory");
        }
        __syncthreads();

        const int collo = st * 64;
        if (collo <= qlo + 31) {                 // warp not fully masked
            const float* kb = Ks + (st & 1) * 4096;
            const float* vb = Vs + (st & 1) * 4608;

            // S = Q K^T   (each K fragment feeds both m-frags)
            float s4[2][8][4];
#pragma unroll
            for (int mf = 0; mf < 2; ++mf)
#pragma unroll
                for (int nt = 0; nt < 8; ++nt)
#pragma unroll
                    for (int j = 0; j < 4; ++j) s4[mf][nt][j] = 0.0f;
#pragma unroll
            for (int ks = 0; ks < 8; ++ks) {
                const uint32_t x0 = ks * 8, x1 = ks * 8 + 4;
#pragma unroll
                for (int nt = 0; nt < 8; ++nt) {
                    uint32_t bk[2];
                    bk[0] = __float_as_uint(kb[ikb[nt] ^ x0]);
                    bk[1] = __float_as_uint(kb[ikb[nt] ^ x1]);
                    mma_tf32(s4[0][nt], qf[0][ks], bk);
                    mma_tf32(s4[1][nt], qf[1][ks], bk);
                }
            }

#pragma unroll
            for (int mf = 0; mf < 2; ++mf) {
                const int qr0 = qlo + mf * 16 + g;
                const bool diag = (collo + 63 > qlo + mf * 16);
#pragma unroll
                for (int nt = 0; nt < 8; ++nt) {
                    s4[mf][nt][0] *= 0.125f; s4[mf][nt][1] *= 0.125f;
                    s4[mf][nt][2] *= 0.125f; s4[mf][nt][3] *= 0.125f;
                    if (diag) {
                        int c0 = collo + nt * 8 + 2 * r;
                        if (c0     > qr0)     s4[mf][nt][0] = -1e30f;
                        if (c0 + 1 > qr0)     s4[mf][nt][1] = -1e30f;
                        if (c0     > qr0 + 8) s4[mf][nt][2] = -1e30f;
                        if (c0 + 1 > qr0 + 8) s4[mf][nt][3] = -1e30f;
                    }
                }

                // online softmax for rows qr0 and qr0+8
                float mx0 = -1e30f, mx1 = -1e30f;
#pragma unroll
                for (int nt = 0; nt < 8; ++nt) {
                    mx0 = fmaxf(mx0, fmaxf(s4[mf][nt][0], s4[mf][nt][1]));
                    mx1 = fmaxf(mx1, fmaxf(s4[mf][nt][2], s4[mf][nt][3]));
                }
                mx0 = fmaxf(mx0, __shfl_xor_sync(0xffffffffu, mx0, 1));
                mx0 = fmaxf(mx0, __shfl_xor_sync(0xffffffffu, mx0, 2));
                mx1 = fmaxf(mx1, __shfl_xor_sync(0xffffffffu, mx1, 1));
                mx1 = fmaxf(mx1, __shfl_xor_sync(0xffffffffu, mx1, 2));

                float mn0 = fmaxf(mM[mf][0], mx0), mn1 = fmaxf(mM[mf][1], mx1);
                float cr0 = __expf(mM[mf][0] - mn0), cr1 = __expf(mM[mf][1] - mn1);
                mM[mf][0] = mn0; mM[mf][1] = mn1;

                float sum0 = 0.0f, sum1 = 0.0f;
#pragma unroll
                for (int nt = 0; nt < 8; ++nt) {
                    float p00 = __expf(s4[mf][nt][0] - mn0);
                    float p01 = __expf(s4[mf][nt][1] - mn0);
                    float p10 = __expf(s4[mf][nt][2] - mn1);
                    float p11 = __expf(s4[mf][nt][3] - mn1);
                    sum0 += p00 + p01;
                    sum1 += p10 + p11;
                    *(float2*)(Pw + (ipw[mf][0] ^ (uint32_t)(nt * 8))) =
                        make_float2(__uint_as_float(cvt_tf32(p00)),
                                    __uint_as_float(cvt_tf32(p01)));
                    *(float2*)(Pw + (ipw[mf][1] ^ (uint32_t)(nt * 8))) =
                        make_float2(__uint_as_float(cvt_tf32(p10)),
                                    __uint_as_float(cvt_tf32(p11)));
                }
                sum0 += __shfl_xor_sync(0xffffffffu, sum0, 1);
                sum0 += __shfl_xor_sync(0xffffffffu, sum0, 2);
                sum1 += __shfl_xor_sync(0xffffffffu, sum1, 1);
                sum1 += __shfl_xor_sync(0xffffffffu, sum1, 2);
                lL[mf][0] = lL[mf][0] * cr0 + sum0;
                lL[mf][1] = lL[mf][1] * cr1 + sum1;

#pragma unroll
                for (int dt = 0; dt < 8; ++dt) {
                    o[mf][dt][0] *= cr0; o[mf][dt][1] *= cr0;
                    o[mf][dt][2] *= cr1; o[mf][dt][3] *= cr1;
                }
            }
            __syncwarp();

            // O += P V   (each V fragment feeds both m-frags)
#pragma unroll
            for (int ks = 0; ks < 8; ++ks) {
                const uint32_t x0 = ks * 8, x1 = ks * 8 + 4;
                uint32_t pa[2][4];
#pragma unroll
                for (int mf = 0; mf < 2; ++mf) {
                    pa[mf][0] = __float_as_uint(Pw[ipa[mf][0] ^ x0]);
                    pa[mf][1] = __float_as_uint(Pw[ipa[mf][1] ^ x0]);
                    pa[mf][2] = __float_as_uint(Pw[ipa[mf][0] ^ x1]);
                    pa[mf][3] = __float_as_uint(Pw[ipa[mf][1] ^ x1]);
                }
#pragma unroll
                for (int dt = 0; dt < 8; ++dt) {
                    uint32_t bv[2];
                    bv[0] = __float_as_uint(vb[(ks * 8 + r) * 72 + dt * 8 + g]);
                    bv[1] = __float_as_uint(vb[(ks * 8 + r + 4) * 72 + dt * 8 + g]);
                    mma_tf32(o[0][dt], pa[0], bv);
                    mma_tf32(o[1][dt], pa[1], bv);
                }
            }
            __syncwarp();   // Pw reads done before next tile's stores
        }
        __syncthreads();   // protect K/V buffers before next iteration
    }

    // finalize: write tf32-rounded output (A operand of proj GEMM)
#pragma unroll
    for (int mf = 0; mf < 2; ++mf) {
        float li0 = 1.0f / lL[mf][0], li1 = 1.0f / lL[mf][1];
        int t0 = qb * 256 + wid * 32 + mf * 16 + g;
        float* ob = gatt + ((size_t)b * Tq + t0) * Cq + h * 64;
#pragma unroll
        for (int dt = 0; dt < 8; ++dt) {
            int cc = dt * 8 + 2 * r;
            *(float2*)(ob + cc) =
                make_float2(__uint_as_float(cvt_tf32(o[mf][dt][0] * li0)),
                            __uint_as_float(cvt_tf32(o[mf][dt][1] * li0)));
            *(float2*)(ob + 8 * Cq + cc) =
                make_float2(__uint_as_float(cvt_tf32(o[mf][dt][2] * li1)),
                            __uint_as_float(cvt_tf32(o[mf][dt][3] * li1)));
        }
    }
}

// ---------------------------------------------------------------------------
// Launch
// ---------------------------------------------------------------------------
extern "C" void kernel_launch(void* const* d_in, const int* in_sizes, int n_in,
                              void* d_out, int out_size)
{
    const float* x      = (const float*)d_in[0];
    const float* w_qkv  = (const float*)d_in[1];
    const float* w_proj = (const float*)d_in[2];
    float* out = (float*)d_out;

    float *qkv, *q, *k, *v, *att, *xr, *wqr, *wpr;
    cudaGetSymbolAddress((void**)&qkv, g_qkv);
    cudaGetSymbolAddress((void**)&q, g_q);
    cudaGetSymbolAddress((void**)&k, g_k);
    cudaGetSymbolAddress((void**)&v, g_v);
    cudaGetSymbolAddress((void**)&att, g_att);
    cudaGetSymbolAddress((void**)&xr, g_xr);
    cudaGetSymbolAddress((void**)&wqr, g_wqkv_r);
    cudaGetSymbolAddress((void**)&wpr, g_wproj_r);

    const int M = Bq * Tq;  // 8192

    cudaFuncSetAttribute(gemm_tf32, cudaFuncAttributeMaxDynamicSharedMemorySize,
                         GEMM_SMEM_BYTES);
    cudaFuncSetAttribute(attn_mma, cudaFuncAttributeMaxDynamicSharedMemorySize,
                         ATTN2_SMEM_BYTES);

    // 0. tf32-round GEMM operands
    round_tf32_k<<<(M * Cq / 4 + 255) / 256, 256>>>(x, xr, M * Cq / 4);
    round_tf32_k<<<(3 * Cq * Cq / 4 + 255) / 256, 256>>>(w_qkv, wqr, 3 * Cq * Cq / 4);
    round_tf32_k<<<(Cq * Cq / 4 + 255) / 256, 256>>>(w_proj, wpr, Cq * Cq / 4);

    // 1. qkv = x @ w_qkv^T
    gemm_tf32<<<dim3((3 * Cq) / 128, M / 128), 128, GEMM_SMEM_BYTES>>>(
        xr, wqr, qkv, M, 3 * Cq, Cq);

    // 2. RoPE + scatter (tf32-rounded q/k/v)
    rope_scatter<<<(Bq * Tq * Hq * 32) / 256, 256>>>();

    // 3. Tensor-core causal flash attention (q-tile 256)
    attn_mma<<<dim3(Tq / 256, Hq, Bq), 256, ATTN2_SMEM_BYTES>>>(q, k, v, att);

    // 4. out = att @ w_proj^T
    gemm_tf32<<<dim3(Cq / 128, M / 128), 128, GEMM_SMEM_BYTES>>>(
        att, wpr, out, M, Cq, Cq);
}

// round 17
// speedup vs baseline: 1.1513x; 1.1414x over previous
#include <cuda_runtime.h>
#include <math.h>
#include <cstdint>

// Problem dims
#define Bq 8
#define Tq 1024
#define Cq 768
#define Hq 12
#define Dq 64

// Scratch (device globals: allocation-free rule)
__device__ float g_q[(size_t)Bq * Hq * Tq * Dq];    // [B][H][T][D] (tf32-rounded)
__device__ float g_k[(size_t)Bq * Hq * Tq * Dq];
__device__ float g_v[(size_t)Bq * Hq * Tq * Dq];
__device__ float g_att[(size_t)Bq * Tq * Cq];       // [B][T][C]   (tf32-rounded)
__device__ float g_xr[(size_t)Bq * Tq * Cq];        // rounded x
__device__ float g_wqkv_r[(size_t)3 * Cq * Cq];     // rounded w_qkv
__device__ float g_wproj_r[(size_t)Cq * Cq];        // rounded w_proj
__device__ float g_tab[(size_t)Tq * 32 * 2];        // (cos,sin) per (t,i)

// ---------------------------------------------------------------------------
// Helpers
// ---------------------------------------------------------------------------
__device__ __forceinline__ uint32_t smem_u32(const void* p) {
    uint32_t a;
    asm("{ .reg .u64 t; cvta.to.shared.u64 t, %1; cvt.u32.u64 %0, t; }"
        : "=r"(a) : "l"(p));
    return a;
}

__device__ __forceinline__ uint32_t cvt_tf32(float v) {
    uint32_t u;
    asm("cvt.rna.tf32.f32 %0, %1;" : "=r"(u) : "f"(v));
    return u;
}

__device__ __forceinline__ float rtf(float v) {
    return __uint_as_float(cvt_tf32(v));
}

__device__ __forceinline__ void mma_tf32(float* d, const uint32_t* a,
                                         const uint32_t* b) {
    asm volatile(
        "mma.sync.aligned.m16n8k8.row.col.f32.tf32.tf32.f32 "
        "{%0,%1,%2,%3}, {%4,%5,%6,%7}, {%8,%9}, {%0,%1,%2,%3};"
        : "+f"(d[0]), "+f"(d[1]), "+f"(d[2]), "+f"(d[3])
        : "r"(a[0]), "r"(a[1]), "r"(a[2]), "r"(a[3]), "r"(b[0]), "r"(b[1]));
}

// XOR-swizzled float index: row-major [s][64], 16B chunks XORed by (s&7)
__device__ __forceinline__ int swz(int s, int d) {
    return s * 64 + ((((d >> 2) ^ (s & 7)) << 2) | (d & 3));
}

// ---------------------------------------------------------------------------
// Round-to-tf32 copy kernel (n divisible by 4)
// ---------------------------------------------------------------------------
__global__ __launch_bounds__(256) void round_tf32_k(const float* __restrict__ in,
                                                    float* __restrict__ out, int n4)
{
    int i = blockIdx.x * 256 + threadIdx.x;
    if (i < n4) {
        float4 v = ((const float4*)in)[i];
        v.x = rtf(v.x); v.y = rtf(v.y); v.z = rtf(v.z); v.w = rtf(v.w);
        ((float4*)out)[i] = v;
    }
}

// ---------------------------------------------------------------------------
// RoPE cos/sin table: g_tab[t][i] = (cos, sin) of t * 10000^(-i/32)
// ---------------------------------------------------------------------------
__global__ __launch_bounds__(256) void rope_tables()
{
    int idx = blockIdx.x * 256 + threadIdx.x;   // t*32 + i
    int i = idx & 31;
    int t = idx >> 5;
    float ang = (float)t * exp2f(-(float)i * (13.2877123795494936f / 32.0f));
    float s, c;
    sincosf(ang, &s, &c);
    g_tab[idx * 2]     = c;
    g_tab[idx * 2 + 1] = s;
}

// ---------------------------------------------------------------------------
// QKV GEMM + fused RoPE epilogue.
// C-space: M=8192 rows (tokens), N=2304 cols (36 groups of 64 = one head each;
// groups 0-11 = q heads, 12-23 = k heads, 24-35 = v heads).
// BM=128, BN=128, BK=32, 128 threads (4 warps 2x2, warp tile 64x64 = 1 head).
// Epilogue applies rotation from g_tab in registers and scatters tf32-rounded
// q/k/v into [B][H][T][D].
// ---------------------------------------------------------------------------
#define GEMM_SMEM_BYTES (4 * 16384)

__global__ __launch_bounds__(128, 2)
void gemm_qkv_rope(const float* __restrict__ A, const float* __restrict__ W,
                   float* __restrict__ gq, float* __restrict__ gk,
                   float* __restrict__ gv)
{
    extern __shared__ float sm[];
    const uint32_t sb = smem_u32(sm);
    const int K = Cq;

    const int tid = threadIdx.x;
    const int wid = tid >> 5;
    const int lane = tid & 31;
    const int g = lane >> 2;
    const int r = lane & 3;
    const int wm = wid & 1;
    const int wn = wid >> 1;
    const int bm = blockIdx.y * 128;
    const int nK = K >> 5;                 // 24

    const int c4 = tid & 7;
    const int r0 = tid >> 3;
    const float* Ag = A + (size_t)(bm + r0) * K + c4 * 4;
    const float* Wg = W + (size_t)(blockIdx.x * 128 + r0) * K + c4 * 4;

    uint32_t ia0[4][2], ib0[8];
#pragma unroll
    for (int mi = 0; mi < 4; ++mi) {
        int r1 = wm * 64 + mi * 16 + g;
        uint32_t lo = ((r1 & 7) << 2) + r;
        ia0[mi][0] = r1 * 32 + lo;
        ia0[mi][1] = (r1 + 8) * 32 + lo;
    }
#pragma unroll
    for (int ni = 0; ni < 8; ++ni) {
        int n = wn * 64 + ni * 8 + g;
        ib0[ni] = n * 32 + ((n & 7) << 2) + r;
    }

    float acc[4][8][4];
#pragma unroll
    for (int mi = 0; mi < 4; ++mi)
#pragma unroll
        for (int ni = 0; ni < 8; ++ni)
#pragma unroll
            for (int j = 0; j < 4; ++j) acc[mi][ni][j] = 0.0f;

    {
        uint32_t sa = sb;
        uint32_t sw = sb + 32768;
#pragma unroll
        for (int i = 0; i < 8; ++i) {
            int row = r0 + i * 16;
            uint32_t off = row * 128 + ((c4 ^ (row & 7)) << 4);
            asm volatile("cp.async.cg.shared.global [%0], [%1], 16;"
                         :: "r"(sa + off), "l"(Ag + (size_t)i * 16 * K) : "memory");
            asm volatile("cp.async.cg.shared.global [%0], [%1], 16;"
                         :: "r"(sw + off), "l"(Wg + (size_t)i * 16 * K) : "memory");
        }
        asm volatile("cp.async.commit_group;" ::: "memory");
    }

    for (int kt = 0; kt < nK; ++kt) {
        if (kt + 1 < nK) {
            int nb = (kt + 1) & 1;
            uint32_t sa = sb + nb * 16384;
            uint32_t sw = sb + 32768 + nb * 16384;
            const float* ag = Ag + (size_t)(kt + 1) * 32;
            const float* wg = Wg + (size_t)(kt + 1) * 32;
#pragma unroll
            for (int i = 0; i < 8; ++i) {
                int row = r0 + i * 16;
                uint32_t off = row * 128 + ((c4 ^ (row & 7)) << 4);
                asm volatile("cp.async.cg.shared.global [%0], [%1], 16;"
                             :: "r"(sa + off), "l"(ag + (size_t)i * 16 * K) : "memory");
                asm volatile("cp.async.cg.shared.global [%0], [%1], 16;"
                             :: "r"(sw + off), "l"(wg + (size_t)i * 16 * K) : "memory");
            }
            asm volatile("cp.async.commit_group;" ::: "memory");
            asm volatile("cp.async.wait_group 1;" ::: "memory");
        } else {
            asm volatile("cp.async.wait_group 0;" ::: "memory");
        }
        __syncthreads();

        const int buf = kt & 1;
        const float* a = sm + buf * 4096;
        const float* b = sm + 8192 + buf * 4096;

#pragma unroll
        for (int ks = 0; ks < 4; ++ks) {
            const uint32_t x0 = ks * 8, x1 = ks * 8 + 4;

            uint32_t af[4][4];
#pragma unroll
            for (int mi = 0; mi < 4; ++mi) {
                af[mi][0] = __float_as_uint(a[ia0[mi][0] ^ x0]);
                af[mi][1] = __float_as_uint(a[ia0[mi][1] ^ x0]);
                af[mi][2] = __float_as_uint(a[ia0[mi][0] ^ x1]);
                af[mi][3] = __float_as_uint(a[ia0[mi][1] ^ x1]);
            }
            uint32_t bf[8][2];
#pragma unroll
            for (int ni = 0; ni < 8; ++ni) {
                bf[ni][0] = __float_as_uint(b[ib0[ni] ^ x0]);
                bf[ni][1] = __float_as_uint(b[ib0[ni] ^ x1]);
            }
#pragma unroll
            for (int mi = 0; mi < 4; ++mi)
#pragma unroll
                for (int ni = 0; ni < 8; ++ni)
                    mma_tf32(acc[mi][ni], af[mi], bf[ni]);
        }
        __syncthreads();
    }

    // ---- fused RoPE epilogue ----
    const int group = blockIdx.x * 2 + wn;   // 0..35
    const int kind = group / Hq;             // 0=q, 1=k, 2=v
    const int h = group % Hq;
    float* dst = (kind == 0) ? gq : (kind == 1) ? gk : gv;

#pragma unroll
    for (int mi = 0; mi < 4; ++mi) {
        int r1 = bm + wm * 64 + mi * 16 + g;
        int b0 = r1 >> 10;
        int t0 = r1 & (Tq - 1);              // row r1; row r1+8 -> t0+8 (no wrap)
        float* gd = dst + ((size_t)(b0 * Hq + h) * Tq + t0) * 64;

        if (kind == 2) {
            // v: plain rounded store
#pragma unroll
            for (int ni = 0; ni < 8; ++ni) {
                int cc = ni * 8 + 2 * r;
                *(float2*)(gd + cc) =
                    make_float2(rtf(acc[mi][ni][0]), rtf(acc[mi][ni][1]));
                *(float2*)(gd + 512 + cc) =
                    make_float2(rtf(acc[mi][ni][2]), rtf(acc[mi][ni][3]));
            }
        } else {
            // q/k: rotate pairs (d, d+32), d = ni*8+2r (+1), ni 0..3
#pragma unroll
            for (int ni = 0; ni < 4; ++ni) {
                int i0 = ni * 8 + 2 * r;     // even, < 32
                float4 cs0 = *(const float4*)(g_tab + ((size_t)t0 * 32 + i0) * 2);
                float4 cs1 = *(const float4*)(g_tab + ((size_t)(t0 + 8) * 32 + i0) * 2);

                float x1a = acc[mi][ni][0],     x1b = acc[mi][ni][1];
                float x2a = acc[mi][ni + 4][0], x2b = acc[mi][ni + 4][1];
                *(float2*)(gd + i0) =
                    make_float2(rtf(x1a * cs0.x + x2a * cs0.y),
                                rtf(x1b * cs0.z + x2b * cs0.w));
                *(float2*)(gd + i0 + 32) =
                    make_float2(rtf(-x1a * cs0.y + x2a * cs0.x),
                                rtf(-x1b * cs0.w + x2b * cs0.z));

                float y1a = acc[mi][ni][2],     y1b = acc[mi][ni][3];
                float y2a = acc[mi][ni + 4][2], y2b = acc[mi][ni + 4][3];
                *(float2*)(gd + 512 + i0) =
                    make_float2(rtf(y1a * cs1.x + y2a * cs1.y),
                                rtf(y1b * cs1.z + y2b * cs1.w));
                *(float2*)(gd + 512 + i0 + 32) =
                    make_float2(rtf(-y1a * cs1.y + y2a * cs1.x),
                                rtf(-y1b * cs1.w + y2b * cs1.z));
            }
        }
    }
}

// ---------------------------------------------------------------------------
// Generic tf32 GEMM (R13 version) — used for the output projection.
// ---------------------------------------------------------------------------
__global__ __launch_bounds__(128, 2)
void gemm_tf32(const float* __restrict__ A, const float* __restrict__ W,
               float* __restrict__ C, int M, int N, int K)
{
    extern __shared__ float sm[];
    const uint32_t sb = smem_u32(sm);

    const int tid = threadIdx.x;
    const int wid = tid >> 5;
    const int lane = tid & 31;
    const int g = lane >> 2;
    const int r = lane & 3;
    const int wm = wid & 1;
    const int wn = wid >> 1;
    const int bm = blockIdx.y * 128;
    const int bn = blockIdx.x * 128;
    const int nK = K >> 5;

    const int c4 = tid & 7;
    const int r0 = tid >> 3;
    const float* Ag = A + (size_t)(bm + r0) * K + c4 * 4;
    const float* Wg = W + (size_t)(bn + r0) * K + c4 * 4;

    uint32_t ia0[4][2], ib0[8];
#pragma unroll
    for (int mi = 0; mi < 4; ++mi) {
        int r1 = wm * 64 + mi * 16 + g;
        uint32_t lo = ((r1 & 7) << 2) + r;
        ia0[mi][0] = r1 * 32 + lo;
        ia0[mi][1] = (r1 + 8) * 32 + lo;
    }
#pragma unroll
    for (int ni = 0; ni < 8; ++ni) {
        int n = wn * 64 + ni * 8 + g;
        ib0[ni] = n * 32 + ((n & 7) << 2) + r;
    }

    float acc[4][8][4];
#pragma unroll
    for (int mi = 0; mi < 4; ++mi)
#pragma unroll
        for (int ni = 0; ni < 8; ++ni)
#pragma unroll
            for (int j = 0; j < 4; ++j) acc[mi][ni][j] = 0.0f;

    {
        uint32_t sa = sb;
        uint32_t sw = sb + 32768;
#pragma unroll
        for (int i = 0; i < 8; ++i) {
            int row = r0 + i * 16;
            uint32_t off = row * 128 + ((c4 ^ (row & 7)) << 4);
            asm volatile("cp.async.cg.shared.global [%0], [%1], 16;"
                         :: "r"(sa + off), "l"(Ag + (size_t)i * 16 * K) : "memory");
            asm volatile("cp.async.cg.shared.global [%0], [%1], 16;"
                         :: "r"(sw + off), "l"(Wg + (size_t)i * 16 * K) : "memory");
        }
        asm volatile("cp.async.commit_group;" ::: "memory");
    }

    for (int kt = 0; kt < nK; ++kt) {
        if (kt + 1 < nK) {
            int nb = (kt + 1) & 1;
            uint32_t sa = sb + nb * 16384;
            uint32_t sw = sb + 32768 + nb * 16384;
            const float* ag = Ag + (size_t)(kt + 1) * 32;
            const float* wg = Wg + (size_t)(kt + 1) * 32;
#pragma unroll
            for (int i = 0; i < 8; ++i) {
                int row = r0 + i * 16;
                uint32_t off = row * 128 + ((c4 ^ (row & 7)) << 4);
                asm volatile("cp.async.cg.shared.global [%0], [%1], 16;"
                             :: "r"(sa + off), "l"(ag + (size_t)i * 16 * K) : "memory");
                asm volatile("cp.async.cg.shared.global [%0], [%1], 16;"
                             :: "r"(sw + off), "l"(wg + (size_t)i * 16 * K) : "memory");
            }
            asm volatile("cp.async.commit_group;" ::: "memory");
            asm volatile("cp.async.wait_group 1;" ::: "memory");
        } else {
            asm volatile("cp.async.wait_group 0;" ::: "memory");
        }
        __syncthreads();

        const int buf = kt & 1;
        const float* a = sm + buf * 4096;
        const float* b = sm + 8192 + buf * 4096;

#pragma unroll
        for (int ks = 0; ks < 4; ++ks) {
            const uint32_t x0 = ks * 8, x1 = ks * 8 + 4;

            uint32_t af[4][4];
#pragma unroll
            for (int mi = 0; mi < 4; ++mi) {
                af[mi][0] = __float_as_uint(a[ia0[mi][0] ^ x0]);
                af[mi][1] = __float_as_uint(a[ia0[mi][1] ^ x0]);
                af[mi][2] = __float_as_uint(a[ia0[mi][0] ^ x1]);
                af[mi][3] = __float_as_uint(a[ia0[mi][1] ^ x1]);
            }
            uint32_t bf[8][2];
#pragma unroll
            for (int ni = 0; ni < 8; ++ni) {
                bf[ni][0] = __float_as_uint(b[ib0[ni] ^ x0]);
                bf[ni][1] = __float_as_uint(b[ib0[ni] ^ x1]);
            }
#pragma unroll
            for (int mi = 0; mi < 4; ++mi)
#pragma unroll
                for (int ni = 0; ni < 8; ++ni)
                    mma_tf32(acc[mi][ni], af[mi], bf[ni]);
        }
        __syncthreads();
    }

#pragma unroll
    for (int mi = 0; mi < 4; ++mi) {
        int r1 = bm + wm * 64 + mi * 16 + g;
#pragma unroll
        for (int ni = 0; ni < 8; ++ni) {
            int cc = bn + wn * 64 + ni * 8 + r * 2;
            *(float2*)(C + (size_t)r1 * N + cc) =
                make_float2(acc[mi][ni][0], acc[mi][ni][1]);
            *(float2*)(C + (size_t)(r1 + 8) * N + cc) =
                make_float2(acc[mi][ni][2], acc[mi][ni][3]);
        }
    }
}

// ---------------------------------------------------------------------------
// Tensor-core flash attention (causal), tf32 mma.sync.  (R13 version)
// Block = (qb128, h, b): 128 q rows, 256 threads (8 warps x 16 rows).
// kv tiles of 64 keys, double-buffered cp.async.
// smem floats: Ks[2][4096] swizzled | Vs[2][4608] stride 72 | Ps[8192]
// ---------------------------------------------------------------------------
#define ATTN2_SMEM_BYTES 102400

__device__ __forceinline__ void load_kv_tile(uint32_t ksm, uint32_t vsm,
                                             const float* kt, const float* vt,
                                             int tid)
{
    int s = tid >> 2, c0 = tid & 3;
#pragma unroll
    for (int i = 0; i < 4; ++i) {
        int c = c0 + i * 4;
        asm volatile("cp.async.cg.shared.global [%0], [%1], 16;"
                     :: "r"(ksm + s * 256 + ((c ^ (s & 7)) << 4)),
                        "l"(kt + s * 64 + c * 4) : "memory");
        asm volatile("cp.async.cg.shared.global [%0], [%1], 16;"
                     :: "r"(vsm + s * 288 + (c << 4)),
                        "l"(vt + s * 64 + c * 4) : "memory");
    }
    asm volatile("cp.async.commit_group;" ::: "memory");
}

__global__ __launch_bounds__(256) void attn_mma(const float* __restrict__ gq,
                                                const float* __restrict__ gk,
                                                const float* __restrict__ gv,
                                                float* __restrict__ gatt)
{
    extern __shared__ float sm2[];
    float* Ks = sm2;                // [2][4096]
    float* Vs = sm2 + 8192;         // [2][4608], stride 72
    float* Ps = sm2 + 17408;        // [8192] (Q staging, then per-warp P)

    const int tid = threadIdx.x;
    const int wid = tid >> 5;
    const int lane = tid & 31;
    const int g = lane >> 2;
    const int r = lane & 3;
    const int qb = (gridDim.x - 1) - blockIdx.x;   // heavy tiles first
    const int h = blockIdx.y;
    const int b = blockIdx.z;

    const float* qp = gq + ((size_t)(b * Hq + h) * Tq + qb * 128) * 64;
    const float* kp = gk + (size_t)(b * Hq + h) * Tq * 64;
    const float* vp = gv + (size_t)(b * Hq + h) * Tq * 64;
    const int nst = 2 * qb + 2;

    const uint32_t ksm = smem_u32(Ks);
    const uint32_t vsm = smem_u32(Vs);

    // prefetch kv tile 0
    load_kv_tile(ksm, vsm, kp, vp, tid);

    // stage Q (128x64) into Ps with swizzle, then lift fragments to registers
#pragma unroll
    for (int i = 0; i < 8; ++i) {
        int idx = tid + i * 256;
        int s = idx >> 4, c = idx & 15;
        float4 v = *(const float4*)(qp + s * 64 + c * 4);
        *(float4*)(Ps + s * 64 + ((c ^ (s & 7)) << 2)) = v;
    }
    __syncthreads();
    uint32_t qf[8][4];
    {
        int q0 = wid * 16 + g;
#pragma unroll
        for (int ks = 0; ks < 8; ++ks) {
            qf[ks][0] = __float_as_uint(Ps[swz(q0, ks * 8 + r)]);
            qf[ks][1] = __float_as_uint(Ps[swz(q0 + 8, ks * 8 + r)]);
            qf[ks][2] = __float_as_uint(Ps[swz(q0, ks * 8 + r + 4)]);
            qf[ks][3] = __float_as_uint(Ps[swz(q0 + 8, ks * 8 + r + 4)]);
        }
    }
    __syncthreads();

    uint32_t ikb[8];
#pragma unroll
    for (int nt = 0; nt < 8; ++nt) {
        int row = nt * 8 + g;
        ikb[nt] = row * 64 + ((row & 7) << 2) + r;
    }
    const uint32_t ipa0 = g * 64 + ((g & 7) << 2) + r;
    const uint32_t ipa1 = (g + 8) * 64 + ((g & 7) << 2) + r;
    const uint32_t pw_lo = (((r >> 1) ^ (g & 7)) << 2) + ((2 * r) & 3);
    const uint32_t ipw0 = g * 64 + pw_lo;
    const uint32_t ipw1 = (g + 8) * 64 + pw_lo;

    float m0 = -1e30f, m1 = -1e30f, l0 = 0.0f, l1 = 0.0f;
    float o[8][4];
#pragma unroll
    for (int dt = 0; dt < 8; ++dt)
#pragma unroll
        for (int j = 0; j < 4; ++j) o[dt][j] = 0.0f;

    float* Pw = Ps + wid * 1024;
    const int qlo = qb * 128 + wid * 16;
    const int qr0 = qlo + g;

    for (int st = 0; st < nst; ++st) {
        if (st + 1 < nst) {
            load_kv_tile(ksm + ((st + 1) & 1) * 16384, vsm + ((st + 1) & 1) * 18432,
                         kp + (size_t)(st + 1) * 4096, vp + (size_t)(st + 1) * 4096, tid);
            asm volatile("cp.async.wait_group 1;" ::: "memory");
        } else {
            asm volatile("cp.async.wait_group 0;" ::: "memory");
        }
        __syncthreads();

        const int collo = st * 64;
        if (collo <= qlo + 15) {                 // warp not fully masked
            const float* kb = Ks + (st & 1) * 4096;
            const float* vb = Vs + (st & 1) * 4608;

            // S = Q K^T
            float s4[8][4];
#pragma unroll
            for (int nt = 0; nt < 8; ++nt)
#pragma unroll
                for (int j = 0; j < 4; ++j) s4[nt][j] = 0.0f;
#pragma unroll
            for (int ks = 0; ks < 8; ++ks) {
                const uint32_t x0 = ks * 8, x1 = ks * 8 + 4;
#pragma unroll
                for (int nt = 0; nt < 8; ++nt) {
                    uint32_t bk[2];
                    bk[0] = __float_as_uint(kb[ikb[nt] ^ x0]);
                    bk[1] = __float_as_uint(kb[ikb[nt] ^ x1]);
                    mma_tf32(s4[nt], qf[ks], bk);
                }
            }

            const bool diag = (collo + 63 > qlo);
#pragma unroll
            for (int nt = 0; nt < 8; ++nt) {
                s4[nt][0] *= 0.125f; s4[nt][1] *= 0.125f;
                s4[nt][2] *= 0.125f; s4[nt][3] *= 0.125f;
                if (diag) {
                    int c0 = collo + nt * 8 + 2 * r;
                    if (c0     > qr0)     s4[nt][0] = -1e30f;
                    if (c0 + 1 > qr0)     s4[nt][1] = -1e30f;
                    if (c0     > qr0 + 8) s4[nt][2] = -1e30f;
                    if (c0 + 1 > qr0 + 8) s4[nt][3] = -1e30f;
                }
            }

            // online softmax (rows qr0 and qr0+8)
            float mx0 = -1e30f, mx1 = -1e30f;
#pragma unroll
            for (int nt = 0; nt < 8; ++nt) {
                mx0 = fmaxf(mx0, fmaxf(s4[nt][0], s4[nt][1]));
                mx1 = fmaxf(mx1, fmaxf(s4[nt][2], s4[nt][3]));
            }
            mx0 = fmaxf(mx0, __shfl_xor_sync(0xffffffffu, mx0, 1));
            mx0 = fmaxf(mx0, __shfl_xor_sync(0xffffffffu, mx0, 2));
            mx1 = fmaxf(mx1, __shfl_xor_sync(0xffffffffu, mx1, 1));
            mx1 = fmaxf(mx1, __shfl_xor_sync(0xffffffffu, mx1, 2));

            float mn0 = fmaxf(m0, mx0), mn1 = fmaxf(m1, mx1);
            float cr0 = __expf(m0 - mn0), cr1 = __expf(m1 - mn1);
            m0 = mn0; m1 = mn1;

            float sum0 = 0.0f, sum1 = 0.0f;
#pragma unroll
            for (int nt = 0; nt < 8; ++nt) {
                float p00 = __expf(s4[nt][0] - m0);
                float p01 = __expf(s4[nt][1] - m0);
                float p10 = __expf(s4[nt][2] - m1);
                float p11 = __expf(s4[nt][3] - m1);
                sum0 += p00 + p01;
                sum1 += p10 + p11;
                *(float2*)(Pw + (ipw0 ^ (uint32_t)(nt * 8))) =
                    make_float2(rtf(p00), rtf(p01));
                *(float2*)(Pw + (ipw1 ^ (uint32_t)(nt * 8))) =
                    make_float2(rtf(p10), rtf(p11));
            }
            sum0 += __shfl_xor_sync(0xffffffffu, sum0, 1);
            sum0 += __shfl_xor_sync(0xffffffffu, sum0, 2);
            sum1 += __shfl_xor_sync(0xffffffffu, sum1, 1);
            sum1 += __shfl_xor_sync(0xffffffffu, sum1, 2);
            l0 = l0 * cr0 + sum0;
            l1 = l1 * cr1 + sum1;

#pragma unroll
            for (int dt = 0; dt < 8; ++dt) {
                o[dt][0] *= cr0; o[dt][1] *= cr0;
                o[dt][2] *= cr1; o[dt][3] *= cr1;
            }
            __syncwarp();

            // O += P V
#pragma unroll
            for (int ks = 0; ks < 8; ++ks) {
                const uint32_t x0 = ks * 8, x1 = ks * 8 + 4;
                uint32_t pa[4];
                pa[0] = __float_as_uint(Pw[ipa0 ^ x0]);
                pa[1] = __float_as_uint(Pw[ipa1 ^ x0]);
                pa[2] = __float_as_uint(Pw[ipa0 ^ x1]);
                pa[3] = __float_as_uint(Pw[ipa1 ^ x1]);
#pragma unroll
                for (int dt = 0; dt < 8; ++dt) {
                    uint32_t bv[2];
                    bv[0] = __float_as_uint(vb[(ks * 8 + r) * 72 + dt * 8 + g]);
                    bv[1] = __float_as_uint(vb[(ks * 8 + r + 4) * 72 + dt * 8 + g]);
                    mma_tf32(o[dt], pa, bv);
                }
            }
        }
        __syncthreads();   // protect K/V buffers & Ps before next iteration
    }

    // finalize: write tf32-rounded output (A operand of proj GEMM)
    float li0 = 1.0f / l0, li1 = 1.0f / l1;
    int t0 = qb * 128 + wid * 16 + g;
    float* ob = gatt + ((size_t)b * Tq + t0) * Cq + h * 64;
#pragma unroll
    for (int dt = 0; dt < 8; ++dt) {
        int cc = dt * 8 + 2 * r;
        *(float2*)(ob + cc) =
            make_float2(rtf(o[dt][0] * li0), rtf(o[dt][1] * li0));
        *(float2*)(ob + 8 * Cq + cc) =
            make_float2(rtf(o[dt][2] * li1), rtf(o[dt][3] * li1));
    }
}

// ---------------------------------------------------------------------------
// Launch
// ---------------------------------------------------------------------------
extern "C" void kernel_launch(void* const* d_in, const int* in_sizes, int n_in,
                              void* d_out, int out_size)
{
    const float* x      = (const float*)d_in[0];
    const float* w_qkv  = (const float*)d_in[1];
    const float* w_proj = (const float*)d_in[2];
    float* out = (float*)d_out;

    float *q, *k, *v, *att, *xr, *wqr, *wpr;
    cudaGetSymbolAddress((void**)&q, g_q);
    cudaGetSymbolAddress((void**)&k, g_k);
    cudaGetSymbolAddress((void**)&v, g_v);
    cudaGetSymbolAddress((void**)&att, g_att);
    cudaGetSymbolAddress((void**)&xr, g_xr);
    cudaGetSymbolAddress((void**)&wqr, g_wqkv_r);
    cudaGetSymbolAddress((void**)&wpr, g_wproj_r);

    const int M = Bq * Tq;  // 8192

    cudaFuncSetAttribute(gemm_qkv_rope, cudaFuncAttributeMaxDynamicSharedMemorySize,
                         GEMM_SMEM_BYTES);
    cudaFuncSetAttribute(gemm_tf32, cudaFuncAttributeMaxDynamicSharedMemorySize,
                         GEMM_SMEM_BYTES);
    cudaFuncSetAttribute(attn_mma, cudaFuncAttributeMaxDynamicSharedMemorySize,
                         ATTN2_SMEM_BYTES);

    // 0. rope tables + tf32-round GEMM operands
    rope_tables<<<(Tq * 32) / 256, 256>>>();
    round_tf32_k<<<(M * Cq / 4 + 255) / 256, 256>>>(x, xr, M * Cq / 4);
    round_tf32_k<<<(3 * Cq * Cq / 4 + 255) / 256, 256>>>(w_qkv, wqr, 3 * Cq * Cq / 4);
    round_tf32_k<<<(Cq * Cq / 4 + 255) / 256, 256>>>(w_proj, wpr, Cq * Cq / 4);

    // 1. qkv = x @ w_qkv^T, fused RoPE + scatter to [B][H][T][D]
    gemm_qkv_rope<<<dim3((3 * Cq) / 128, M / 128), 128, GEMM_SMEM_BYTES>>>(
        xr, wqr, q, k, v);

    // 2. Tensor-core causal flash attention
    attn_mma<<<dim3(Tq / 128, Hq, Bq), 256, ATTN2_SMEM_BYTES>>>(q, k, v, att);

    // 3. out = att @ w_proj^T
    gemm_tf32<<<dim3(Cq / 128, M / 128), 128, GEMM_SMEM_BYTES>>>(
        att, wpr, out, M, Cq, Cq);
}